// round 4
// baseline (speedup 1.0000x reference)
#include <cuda_runtime.h>
#include <math.h>
#include <stdint.h>

#define TT 1024
#define BB 64
#define NIN 128
#define NHID 512
#define WLD (NHID + NIN + 1)   // 641, w_rec row stride

// scratch: precomputed input projection xin[t][b][h]  (128 MB)
__device__ float g_xin[(size_t)TT * BB * NHID];
// per-block arrival epochs (flag barrier), zeroed each launch
__device__ volatile unsigned int g_arrive[128];

__global__ void zero_bar_kernel() {
  if (threadIdx.x < 128) g_arrive[threadIdx.x] = 0u;
}

// ---------------------------------------------------------------------------
// Kernel 1: xin[m][n] = sum_i x[m][i] * w_x[n][i] + bias[n]   (unchanged)
// ---------------------------------------------------------------------------
__global__ __launch_bounds__(256) void precompute_kernel(
    const float* __restrict__ x, const float* __restrict__ w_rec) {
  extern __shared__ float sm[];
  float* xs = sm;                    // [64][132]
  float* ws = sm + 64 * 132;         // [128][68]
  float* bs = ws + 128 * 68;         // [64]

  const int m0 = blockIdx.x * 64;
  const int n0 = blockIdx.y * 64;
  const int tid = threadIdx.x;

  const float4* xg = (const float4*)(x + (size_t)m0 * NIN);
  for (int i = tid; i < 64 * 32; i += 256) {
    int r = i >> 5, c4 = i & 31;
    float4 v = xg[r * 32 + c4];
    *(float4*)&xs[r * 132 + c4 * 4] = v;
  }
  for (int i = tid; i < 64 * 128; i += 256) {
    int h = i >> 7, k = i & 127;
    ws[k * 68 + h] = w_rec[(size_t)(n0 + h) * WLD + NHID + k];
  }
  if (tid < 64) bs[tid] = w_rec[(size_t)(n0 + tid) * WLD + NHID + NIN];
  __syncthreads();

  const int ty = tid >> 4;
  const int tx = tid & 15;

  float acc[4][4];
#pragma unroll
  for (int u = 0; u < 4; u++)
#pragma unroll
    for (int v = 0; v < 4; v++) acc[u][v] = 0.0f;

  const float* xr0 = &xs[(ty * 4 + 0) * 132];
  const float* xr1 = &xs[(ty * 4 + 1) * 132];
  const float* xr2 = &xs[(ty * 4 + 2) * 132];
  const float* xr3 = &xs[(ty * 4 + 3) * 132];

#pragma unroll 4
  for (int k = 0; k < 128; k++) {
    float a0 = xr0[k], a1 = xr1[k], a2 = xr2[k], a3 = xr3[k];
    float4 bv = *(const float4*)&ws[k * 68 + tx * 4];
    acc[0][0] += a0 * bv.x; acc[0][1] += a0 * bv.y; acc[0][2] += a0 * bv.z; acc[0][3] += a0 * bv.w;
    acc[1][0] += a1 * bv.x; acc[1][1] += a1 * bv.y; acc[1][2] += a1 * bv.z; acc[1][3] += a1 * bv.w;
    acc[2][0] += a2 * bv.x; acc[2][1] += a2 * bv.y; acc[2][2] += a2 * bv.z; acc[2][3] += a2 * bv.w;
    acc[3][0] += a3 * bv.x; acc[3][1] += a3 * bv.y; acc[3][2] += a3 * bv.z; acc[3][3] += a3 * bv.w;
  }

  float4 bias4 = *(const float4*)&bs[tx * 4];
#pragma unroll
  for (int u = 0; u < 4; u++) {
    float4 r;
    r.x = acc[u][0] + bias4.x;
    r.y = acc[u][1] + bias4.y;
    r.z = acc[u][2] + bias4.z;
    r.w = acc[u][3] + bias4.w;
    *(float4*)&g_xin[(size_t)(m0 + ty * 4 + u) * NHID + n0 + tx * 4] = r;
  }
}

// ---------------------------------------------------------------------------
// Kernel 2: persistent recurrence, v3.
//   128 blocks x 256 threads; block = (bhg = bid&31 -> 16 h-rows,
//   bbg = bid>>5 -> 16 batches). w_h slice permanent in registers.
//   Per step: skewed k-major h stage (conflict-free), xin prefetch,
//   2 LDS.128 + 32 FFMA per k-iter (K-split 32), thread-major STS.128
//   partials, smem reduce + tanh, flag-based group barrier (fan-in 32).
// ---------------------------------------------------------------------------
#define HS_STRIDE 36      // floats per k-row (skewed split layout)
#define RED_STRIDE 36     // floats per writer-thread row

__global__ __launch_bounds__(256, 1) void rnn_rec_kernel(
    const float* __restrict__ h0, const float* __restrict__ w_rec,
    float* __restrict__ out) {
  extern __shared__ float sm[];
  float* hs  = sm;                        // [512][HS_STRIDE]
  float* red = sm + 512 * HS_STRIDE;      // [256][RED_STRIDE]

  const int tid = threadIdx.x;
  const int bid = blockIdx.x;
  const int bhg = bid & 31;   // 32 h-groups of 16 rows
  const int bbg = bid >> 5;   // 4 independent batch groups of 16
  const int hblk = bhg * 16;
  const int b0 = bbg * 16;

  const int th = tid & 3;            // 4 h-subgroups of 4 rows
  const int tb = (tid >> 2) & 1;     // 2 batch halves of 8
  const int kq = tid >> 3;           // 0..31, k = kq + 32*i

  // persistent W registers: rows hblk + th*4 + j, k = kq + 32*i
  float Wreg[4][16];
#pragma unroll
  for (int j = 0; j < 4; j++) {
    const float* wrow = w_rec + (size_t)(hblk + th * 4 + j) * WLD + kq;
#pragma unroll
    for (int i = 0; i < 16; i++) Wreg[j][i] = wrow[i * 32];
  }

  // h staging: lane covers one batch row x 32 consecutive k, skewed layout
  const int st_bl = tid & 15;                 // batch row 0..15
  const int st_kc = tid >> 4;                 // k chunk 0..15 (32 k each)
  const int st_sk = (st_kc & 1) * 8;          // skew per odd k-chunk
  const int st_boff = (st_bl & 7) + ((st_bl >> 3) & 1) * 16 + st_sk;

  // reduce/epilogue output index (h fastest -> coalesced)
  const int o_h = tid & 15;                    // = th'*4 + j'
  const int o_b = tid >> 4;                    // = tb'*8 + b'
  const int r_w = ((o_b >> 3) * 4 + (o_h >> 2));   // writer (tb,th) part
  const int r_off = (o_b & 7) * 4 + (o_h & 3);     // b'*4 + j'

  const int tbofs = 16 * tb;

  for (int t = 0; t < TT; t++) {
    const float* hp = (t == 0) ? h0 : (out + (size_t)(t - 1) * BB * NHID);

    // stage h slice: gmem (b-major) -> smem (k-major, skewed split layout)
    const float* src = hp + (size_t)(b0 + st_bl) * NHID + st_kc * 32;
#pragma unroll
    for (int m4 = 0; m4 < 8; m4++) {
      float4 v = __ldcg((const float4*)(src + m4 * 4));
      int kb = st_kc * 32 + m4 * 4;
      hs[(kb + 0) * HS_STRIDE + st_boff] = v.x;
      hs[(kb + 1) * HS_STRIDE + st_boff] = v.y;
      hs[(kb + 2) * HS_STRIDE + st_boff] = v.z;
      hs[(kb + 3) * HS_STRIDE + st_boff] = v.w;
    }

    // prefetch xin (independent of h) -> hidden under the dot loop
    const size_t oidx =
        (size_t)t * BB * NHID + (size_t)(b0 + o_b) * NHID + hblk + o_h;
    const float u = __ldcg(&g_xin[oidx]);

    __syncthreads();

    float acc[4][8];
#pragma unroll
    for (int j = 0; j < 4; j++)
#pragma unroll
      for (int b = 0; b < 8; b++) acc[j][b] = 0.0f;

#pragma unroll
    for (int i = 0; i < 16; i++) {
      // k = kq + 32*i lives in chunk i (parity skew 8*(i&1))
      const float* hrow = &hs[(kq + 32 * i) * HS_STRIDE + tbofs + 8 * (i & 1)];
      float4 lo = *(const float4*)(hrow);
      float4 hi = *(const float4*)(hrow + 4);
      float hb0 = lo.x, hb1 = lo.y, hb2 = lo.z, hb3 = lo.w;
      float hb4 = hi.x, hb5 = hi.y, hb6 = hi.z, hb7 = hi.w;
#pragma unroll
      for (int j = 0; j < 4; j++) {
        const float w = Wreg[j][i];
        acc[j][0] += w * hb0; acc[j][1] += w * hb1;
        acc[j][2] += w * hb2; acc[j][3] += w * hb3;
        acc[j][4] += w * hb4; acc[j][5] += w * hb5;
        acc[j][6] += w * hb6; acc[j][7] += w * hb7;
      }
    }

    // partials, thread-major: red[tid][b*4 + j], float4 over j (conflict-free)
#pragma unroll
    for (int b = 0; b < 8; b++) {
      float4 v;
      v.x = acc[0][b]; v.y = acc[1][b]; v.z = acc[2][b]; v.w = acc[3][b];
      *(float4*)&red[tid * RED_STRIDE + b * 4] = v;
    }
    __syncthreads();

    // reduce 32 K-partials for output (o_h, o_b); writer w = q*8 + r_w
    float s0 = 0.f, s1 = 0.f, s2 = 0.f, s3 = 0.f;
#pragma unroll
    for (int q = 0; q < 32; q += 4) {
      s0 += red[(q + 0) * 8 * RED_STRIDE + r_w * RED_STRIDE + r_off];
      s1 += red[(q + 1) * 8 * RED_STRIDE + r_w * RED_STRIDE + r_off];
      s2 += red[(q + 2) * 8 * RED_STRIDE + r_w * RED_STRIDE + r_off];
      s3 += red[(q + 3) * 8 * RED_STRIDE + r_w * RED_STRIDE + r_off];
    }
    out[oidx] = tanhf((s0 + s1) + (s2 + s3) + u);

    // release: every thread fences its own store, then flag + group poll
    __threadfence();
    __syncthreads();
    if (tid < 32) {
      if (tid == 0) g_arrive[bid] = (unsigned)(t + 1);
      const unsigned target = (unsigned)(t + 1);
      while (!__all_sync(0xffffffffu, g_arrive[bbg * 32 + tid] >= target)) {
      }
      __threadfence();
    }
    __syncthreads();
  }
}

// ---------------------------------------------------------------------------
extern "C" void kernel_launch(void* const* d_in, const int* in_sizes, int n_in,
                              void* d_out, int out_size) {
  const float* x     = (const float*)d_in[0];  // (T,B,NIN) f32
  const float* h0    = (const float*)d_in[1];  // (B,NH)    f32
  const float* w_rec = (const float*)d_in[2];  // (NH, NH+NIN+1) f32
  float* out = (float*)d_out;                  // (T,B,NH)  f32

  const int pre_smem = (64 * 132 + 128 * 68 + 64) * (int)sizeof(float);  // 68864 B
  const int rec_smem =
      (512 * HS_STRIDE + 256 * RED_STRIDE) * (int)sizeof(float);         // 110592 B
  cudaFuncSetAttribute(precompute_kernel,
                       cudaFuncAttributeMaxDynamicSharedMemorySize, pre_smem);
  cudaFuncSetAttribute(rnn_rec_kernel,
                       cudaFuncAttributeMaxDynamicSharedMemorySize, rec_smem);

  zero_bar_kernel<<<1, 128>>>();

  dim3 pgrid(TT * BB / 64, NHID / 64);  // 1024 x 8
  precompute_kernel<<<pgrid, 256, pre_smem>>>(x, w_rec);

  rnn_rec_kernel<<<128, 256, rec_smem>>>(h0, w_rec, out);
}

// round 8
// speedup vs baseline: 2.3377x; 2.3377x over previous
#include <cuda_runtime.h>
#include <math.h>
#include <stdint.h>

#define TT 1024
#define BB 64
#define NIN 128
#define NHID 512
#define WLD (NHID + NIN + 1)   // 641, w_rec row stride

// scratch: precomputed input projection xin[t][b][h]  (128 MB)
__device__ float g_xin[(size_t)TT * BB * NHID];
// per-batch-group arrival counters, each on its own 128B line (4 groups)
__device__ unsigned int g_bar4[4 * 32];

// ---------------------------------------------------------------------------
// Kernel 1: xin[m][n] = sum_i x[m][i] * w_x[n][i] + bias[n]
//   Also zeroes the barrier counters (block (0,0)) -> no separate launch.
// ---------------------------------------------------------------------------
__global__ __launch_bounds__(256) void precompute_kernel(
    const float* __restrict__ x, const float* __restrict__ w_rec) {
  extern __shared__ float sm[];
  float* xs = sm;                    // [64][132]
  float* ws = sm + 64 * 132;         // [128][68]
  float* bs = ws + 128 * 68;         // [64]

  const int m0 = blockIdx.x * 64;
  const int n0 = blockIdx.y * 64;
  const int tid = threadIdx.x;

  if (blockIdx.x == 0 && blockIdx.y == 0 && tid < 4) g_bar4[tid * 32] = 0u;

  const float4* xg = (const float4*)(x + (size_t)m0 * NIN);
  for (int i = tid; i < 64 * 32; i += 256) {
    int r = i >> 5, c4 = i & 31;
    float4 v = xg[r * 32 + c4];
    *(float4*)&xs[r * 132 + c4 * 4] = v;
  }
  for (int i = tid; i < 64 * 128; i += 256) {
    int h = i >> 7, k = i & 127;
    ws[k * 68 + h] = w_rec[(size_t)(n0 + h) * WLD + NHID + k];
  }
  if (tid < 64) bs[tid] = w_rec[(size_t)(n0 + tid) * WLD + NHID + NIN];
  __syncthreads();

  const int ty = tid >> 4;
  const int tx = tid & 15;

  float acc[4][4];
#pragma unroll
  for (int u = 0; u < 4; u++)
#pragma unroll
    for (int v = 0; v < 4; v++) acc[u][v] = 0.0f;

  const float* xr0 = &xs[(ty * 4 + 0) * 132];
  const float* xr1 = &xs[(ty * 4 + 1) * 132];
  const float* xr2 = &xs[(ty * 4 + 2) * 132];
  const float* xr3 = &xs[(ty * 4 + 3) * 132];

#pragma unroll 4
  for (int k = 0; k < 128; k++) {
    float a0 = xr0[k], a1 = xr1[k], a2 = xr2[k], a3 = xr3[k];
    float4 bv = *(const float4*)&ws[k * 68 + tx * 4];
    acc[0][0] += a0 * bv.x; acc[0][1] += a0 * bv.y; acc[0][2] += a0 * bv.z; acc[0][3] += a0 * bv.w;
    acc[1][0] += a1 * bv.x; acc[1][1] += a1 * bv.y; acc[1][2] += a1 * bv.z; acc[1][3] += a1 * bv.w;
    acc[2][0] += a2 * bv.x; acc[2][1] += a2 * bv.y; acc[2][2] += a2 * bv.z; acc[2][3] += a2 * bv.w;
    acc[3][0] += a3 * bv.x; acc[3][1] += a3 * bv.y; acc[3][2] += a3 * bv.z; acc[3][3] += a3 * bv.w;
  }

  float4 bias4 = *(const float4*)&bs[tx * 4];
#pragma unroll
  for (int u = 0; u < 4; u++) {
    float4 r;
    r.x = acc[u][0] + bias4.x;
    r.y = acc[u][1] + bias4.y;
    r.z = acc[u][2] + bias4.z;
    r.w = acc[u][3] + bias4.w;
    *(float4*)&g_xin[(size_t)(m0 + ty * 4 + u) * NHID + n0 + tx * 4] = r;
  }
}

// ---------------------------------------------------------------------------
// Kernel 2: persistent recurrence, v4.
//   128 blocks x 256 threads; block = (bhg = bid&31 -> 16 h-rows,
//   bbg = bid>>5 -> 16 batches). w_h slice permanent in registers.
//   Per step: skewed conflict-free k-major h stage, xin prefetch,
//   2 LDS.128 + 32 FFMA per k-iter (K-split 32), float4 thread-major
//   partial store, smem reduce + tanh, per-group atomic barrier
//   (fan-in 32, nanosleep-backed poll -- R2-proven mechanics).
// ---------------------------------------------------------------------------
#define HS_STRIDE 36      // floats per k-row (skewed split layout)
#define RED_STRIDE 36     // floats per writer-thread row

__global__ __launch_bounds__(256, 1) void rnn_rec_kernel(
    const float* __restrict__ h0, const float* __restrict__ w_rec,
    float* __restrict__ out) {
  extern __shared__ float sm[];
  float* hs  = sm;                        // [512][HS_STRIDE]
  float* red = sm + 512 * HS_STRIDE;      // [256][RED_STRIDE]

  const int tid = threadIdx.x;
  const int bid = blockIdx.x;
  const int bhg = bid & 31;   // 32 h-groups of 16 rows
  const int bbg = bid >> 5;   // 4 independent batch groups of 16
  const int hblk = bhg * 16;
  const int b0 = bbg * 16;

  const int th = tid & 3;            // 4 h-subgroups of 4 rows
  const int tb = (tid >> 2) & 1;     // 2 batch halves of 8
  const int kq = tid >> 3;           // 0..31, k = kq + 32*i

  // persistent W registers: rows hblk + th*4 + j, k = kq + 32*i
  float Wreg[4][16];
#pragma unroll
  for (int j = 0; j < 4; j++) {
    const float* wrow = w_rec + (size_t)(hblk + th * 4 + j) * WLD + kq;
#pragma unroll
    for (int i = 0; i < 16; i++) Wreg[j][i] = wrow[i * 32];
  }

  // h staging: lane covers one batch row x 32 consecutive k, skewed layout
  const int st_bl = tid & 15;                 // batch row 0..15
  const int st_kc = tid >> 4;                 // k chunk 0..15 (32 k each)
  const int st_sk = (st_kc & 1) * 8;          // skew per odd k-chunk
  const int st_boff = (st_bl & 7) + ((st_bl >> 3) & 1) * 16 + st_sk;

  // reduce/epilogue output index (h fastest -> coalesced)
  const int o_h = tid & 15;
  const int o_b = tid >> 4;
  const int r_w = ((o_b >> 3) * 4 + (o_h >> 2));   // writer (tb,th) part
  const int r_off = (o_b & 7) * 4 + (o_h & 3);     // b'*4 + j'

  const int tbofs = 16 * tb;
  unsigned int* bar = &g_bar4[bbg * 32];

  for (int t = 0; t < TT; t++) {
    const float* hp = (t == 0) ? h0 : (out + (size_t)(t - 1) * BB * NHID);

    // stage h slice: gmem (b-major) -> smem (k-major, skewed split layout)
    const float* src = hp + (size_t)(b0 + st_bl) * NHID + st_kc * 32;
#pragma unroll
    for (int m4 = 0; m4 < 8; m4++) {
      float4 v = __ldcg((const float4*)(src + m4 * 4));
      int kb = st_kc * 32 + m4 * 4;
      hs[(kb + 0) * HS_STRIDE + st_boff] = v.x;
      hs[(kb + 1) * HS_STRIDE + st_boff] = v.y;
      hs[(kb + 2) * HS_STRIDE + st_boff] = v.z;
      hs[(kb + 3) * HS_STRIDE + st_boff] = v.w;
    }

    // prefetch xin (independent of h) -> hidden under the dot loop
    const size_t oidx =
        (size_t)t * BB * NHID + (size_t)(b0 + o_b) * NHID + hblk + o_h;
    const float u = __ldcg(&g_xin[oidx]);

    __syncthreads();

    float acc[4][8];
#pragma unroll
    for (int j = 0; j < 4; j++)
#pragma unroll
      for (int b = 0; b < 8; b++) acc[j][b] = 0.0f;

#pragma unroll
    for (int i = 0; i < 16; i++) {
      // k = kq + 32*i lives in chunk i (parity skew 8*(i&1))
      const float* hrow = &hs[(kq + 32 * i) * HS_STRIDE + tbofs + 8 * (i & 1)];
      float4 lo = *(const float4*)(hrow);
      float4 hi = *(const float4*)(hrow + 4);
      float hb0 = lo.x, hb1 = lo.y, hb2 = lo.z, hb3 = lo.w;
      float hb4 = hi.x, hb5 = hi.y, hb6 = hi.z, hb7 = hi.w;
#pragma unroll
      for (int j = 0; j < 4; j++) {
        const float w = Wreg[j][i];
        acc[j][0] += w * hb0; acc[j][1] += w * hb1;
        acc[j][2] += w * hb2; acc[j][3] += w * hb3;
        acc[j][4] += w * hb4; acc[j][5] += w * hb5;
        acc[j][6] += w * hb6; acc[j][7] += w * hb7;
      }
    }

    // partials, thread-major: red[tid][b*4 + j], float4 over j (conflict-free)
#pragma unroll
    for (int b = 0; b < 8; b++) {
      float4 v;
      v.x = acc[0][b]; v.y = acc[1][b]; v.z = acc[2][b]; v.w = acc[3][b];
      *(float4*)&red[tid * RED_STRIDE + b * 4] = v;
    }
    __syncthreads();

    // reduce 32 K-partials for output (o_h, o_b); writer w = q*8 + r_w
    float s0 = 0.f, s1 = 0.f, s2 = 0.f, s3 = 0.f;
#pragma unroll
    for (int q = 0; q < 32; q += 4) {
      s0 += red[(q + 0) * 8 * RED_STRIDE + r_w * RED_STRIDE + r_off];
      s1 += red[(q + 1) * 8 * RED_STRIDE + r_w * RED_STRIDE + r_off];
      s2 += red[(q + 2) * 8 * RED_STRIDE + r_w * RED_STRIDE + r_off];
      s3 += red[(q + 3) * 8 * RED_STRIDE + r_w * RED_STRIDE + r_off];
    }
    out[oidx] = tanhf((s0 + s1) + (s2 + s3) + u);

    // per-group barrier: R2-proven atomic + nanosleep poll, fan-in 32
    __syncthreads();
    __threadfence();
    if (tid == 0) {
      atomicAdd(bar, 1u);
      const unsigned int target = 32u * (unsigned)(t + 1);
      while (*((volatile unsigned int*)bar) < target) {
        __nanosleep(32);
      }
    }
    __syncthreads();
  }
}

// ---------------------------------------------------------------------------
extern "C" void kernel_launch(void* const* d_in, const int* in_sizes, int n_in,
                              void* d_out, int out_size) {
  const float* x     = (const float*)d_in[0];  // (T,B,NIN) f32
  const float* h0    = (const float*)d_in[1];  // (B,NH)    f32
  const float* w_rec = (const float*)d_in[2];  // (NH, NH+NIN+1) f32
  float* out = (float*)d_out;                  // (T,B,NH)  f32

  const int pre_smem = (64 * 132 + 128 * 68 + 64) * (int)sizeof(float);  // 68864 B
  const int rec_smem =
      (512 * HS_STRIDE + 256 * RED_STRIDE) * (int)sizeof(float);         // 110592 B
  cudaFuncSetAttribute(precompute_kernel,
                       cudaFuncAttributeMaxDynamicSharedMemorySize, pre_smem);
  cudaFuncSetAttribute(rnn_rec_kernel,
                       cudaFuncAttributeMaxDynamicSharedMemorySize, rec_smem);

  dim3 pgrid(TT * BB / 64, NHID / 64);  // 1024 x 8
  precompute_kernel<<<pgrid, 256, pre_smem>>>(x, w_rec);

  rnn_rec_kernel<<<128, 256, rec_smem>>>(h0, w_rec, out);
}

// round 9
// speedup vs baseline: 3.6045x; 1.5419x over previous
#include <cuda_runtime.h>
#include <math.h>
#include <stdint.h>

#define TT 1024
#define BB 64
#define NIN 128
#define NHID 512
#define WLD (NHID + NIN + 1)   // 641, w_rec row stride

// scratch: precomputed input projection xin[t][b][h]  (128 MB)
__device__ float g_xin[(size_t)TT * BB * NHID];
// transposed h scratch, double-buffered: [parity][group][k][b]  (256 KB)
__device__ float g_hT[2 * 8 * NHID * 8];
// per-batch-group arrival counters, each on its own 128B line (8 groups)
__device__ unsigned int g_bar8[8 * 32];

// ---------------------------------------------------------------------------
// Kernel 1: xin[m][n] = sum_i x[m][i] * w_x[n][i] + bias[n]
//   Also zeroes the barrier counters (block (0,0)).
// ---------------------------------------------------------------------------
__global__ __launch_bounds__(256) void precompute_kernel(
    const float* __restrict__ x, const float* __restrict__ w_rec) {
  extern __shared__ float sm[];
  float* xs = sm;                    // [64][132]
  float* ws = sm + 64 * 132;         // [128][68]
  float* bs = ws + 128 * 68;         // [64]

  const int m0 = blockIdx.x * 64;
  const int n0 = blockIdx.y * 64;
  const int tid = threadIdx.x;

  if (blockIdx.x == 0 && blockIdx.y == 0 && tid < 8) g_bar8[tid * 32] = 0u;

  const float4* xg = (const float4*)(x + (size_t)m0 * NIN);
  for (int i = tid; i < 64 * 32; i += 256) {
    int r = i >> 5, c4 = i & 31;
    float4 v = xg[r * 32 + c4];
    *(float4*)&xs[r * 132 + c4 * 4] = v;
  }
  for (int i = tid; i < 64 * 128; i += 256) {
    int h = i >> 7, k = i & 127;
    ws[k * 68 + h] = w_rec[(size_t)(n0 + h) * WLD + NHID + k];
  }
  if (tid < 64) bs[tid] = w_rec[(size_t)(n0 + tid) * WLD + NHID + NIN];
  __syncthreads();

  const int ty = tid >> 4;
  const int tx = tid & 15;

  float acc[4][4];
#pragma unroll
  for (int u = 0; u < 4; u++)
#pragma unroll
    for (int v = 0; v < 4; v++) acc[u][v] = 0.0f;

  const float* xr0 = &xs[(ty * 4 + 0) * 132];
  const float* xr1 = &xs[(ty * 4 + 1) * 132];
  const float* xr2 = &xs[(ty * 4 + 2) * 132];
  const float* xr3 = &xs[(ty * 4 + 3) * 132];

#pragma unroll 4
  for (int k = 0; k < 128; k++) {
    float a0 = xr0[k], a1 = xr1[k], a2 = xr2[k], a3 = xr3[k];
    float4 bv = *(const float4*)&ws[k * 68 + tx * 4];
    acc[0][0] += a0 * bv.x; acc[0][1] += a0 * bv.y; acc[0][2] += a0 * bv.z; acc[0][3] += a0 * bv.w;
    acc[1][0] += a1 * bv.x; acc[1][1] += a1 * bv.y; acc[1][2] += a1 * bv.z; acc[1][3] += a1 * bv.w;
    acc[2][0] += a2 * bv.x; acc[2][1] += a2 * bv.y; acc[2][2] += a2 * bv.z; acc[2][3] += a2 * bv.w;
    acc[3][0] += a3 * bv.x; acc[3][1] += a3 * bv.y; acc[3][2] += a3 * bv.z; acc[3][3] += a3 * bv.w;
  }

  float4 bias4 = *(const float4*)&bs[tx * 4];
#pragma unroll
  for (int u = 0; u < 4; u++) {
    float4 r;
    r.x = acc[u][0] + bias4.x;
    r.y = acc[u][1] + bias4.y;
    r.z = acc[u][2] + bias4.z;
    r.w = acc[u][3] + bias4.w;
    *(float4*)&g_xin[(size_t)(m0 + ty * 4 + u) * NHID + n0 + tx * 4] = r;
  }
}

// ---------------------------------------------------------------------------
// Kernel 2: persistent recurrence, v5.
//   128 blocks x 256 threads; block = (bhg = bid&15 -> 32 h-rows,
//   bbg = bid>>4 -> 8 batches). w_h slice permanent in registers (64/thread).
//   h exchanged via k-major double-buffered scratch g_hT -> staging is
//   4 coalesced LDG.128 + 4 conflict-free STS.128 per thread.
//   Dot: K-split 32, per k-iter 2 broadcast LDS.128 + 32 FFMA.
//   Barrier: per-group atomic + nanosleep poll, fan-in 16.
// ---------------------------------------------------------------------------
#define HS_STRIDE 8       // floats per k-row of staged h ([512][8])
#define RED_STRIDE 36     // floats per writer-thread row

__global__ __launch_bounds__(256, 1) void rnn_rec_kernel(
    const float* __restrict__ h0, const float* __restrict__ w_rec,
    float* __restrict__ out) {
  extern __shared__ float sm[];
  float* hs  = sm;                        // [512][8]
  float* red = sm + NHID * HS_STRIDE;     // [256][36]

  const int tid = threadIdx.x;
  const int bid = blockIdx.x;
  const int bhg = bid & 15;   // 16 h-groups of 32 rows
  const int bbg = bid >> 4;   // 8 independent batch groups of 8
  const int hblk = bhg * 32;
  const int b0 = bbg * 8;

  const int th = tid & 7;            // 8 h-subgroups of 4 rows
  const int kq = tid >> 3;           // 0..31, k = kq + 32*i

  // persistent W registers: rows hblk + th*4 + j, k = kq + 32*i
  float Wreg[4][16];
#pragma unroll
  for (int j = 0; j < 4; j++) {
    const float* wrow = w_rec + (size_t)(hblk + th * 4 + j) * WLD + kq;
#pragma unroll
    for (int i = 0; i < 16; i++) Wreg[j][i] = wrow[i * 32];
  }

  // staging: thread covers (kk + 128c, c=0..3) x 4 batches (b4 half)
  const int st_b4 = tid & 1;          // which float4 of the 8-batch row
  const int st_kk = (tid >> 1) & 127; // base k

  // output mapping (h fastest -> out coalesced)
  const int o_h = tid & 31;
  const int o_b = tid >> 5;
  const int r_th = o_h >> 2;         // writer th
  const int r_j = o_h & 3;           // writer j

  float* hT_w_base = g_hT + (size_t)bbg * NHID * 8;   // + parity*8*NHID*8
  unsigned int* bar = &g_bar8[bbg * 32];

  for (int t = 0; t < TT; t++) {
    // ---- stage h(t-1) into hs[k][b] ----
    if (t == 0) {
#pragma unroll
      for (int c = 0; c < 4; c++) {
        int k = st_kk + 128 * c;
#pragma unroll
        for (int j = 0; j < 4; j++) {
          int b = st_b4 * 4 + j;
          hs[k * HS_STRIDE + b] = __ldg(&h0[(size_t)(b0 + b) * NHID + k]);
        }
      }
    } else {
      const float* src =
          g_hT + (size_t)(((t - 1) & 1) * 8 + bbg) * NHID * 8;
#pragma unroll
      for (int c = 0; c < 4; c++) {
        int k = st_kk + 128 * c;
        float4 v = __ldcg((const float4*)(src + k * 8 + st_b4 * 4));
        *(float4*)&hs[k * HS_STRIDE + st_b4 * 4] = v;
      }
    }

    // prefetch xin (independent of h) -> hidden under the dot loop
    const size_t oidx =
        (size_t)t * BB * NHID + (size_t)(b0 + o_b) * NHID + hblk + o_h;
    const float u = __ldcg(&g_xin[oidx]);

    __syncthreads();

    // ---- dot: 16 iters x (2 broadcast LDS.128 + 32 FFMA) ----
    float acc[4][8];
#pragma unroll
    for (int j = 0; j < 4; j++)
#pragma unroll
      for (int b = 0; b < 8; b++) acc[j][b] = 0.0f;

#pragma unroll
    for (int i = 0; i < 16; i++) {
      const float* hrow = &hs[(kq + 32 * i) * HS_STRIDE];
      float4 lo = *(const float4*)(hrow);
      float4 hi = *(const float4*)(hrow + 4);
      float hb0 = lo.x, hb1 = lo.y, hb2 = lo.z, hb3 = lo.w;
      float hb4 = hi.x, hb5 = hi.y, hb6 = hi.z, hb7 = hi.w;
#pragma unroll
      for (int j = 0; j < 4; j++) {
        const float w = Wreg[j][i];
        acc[j][0] += w * hb0; acc[j][1] += w * hb1;
        acc[j][2] += w * hb2; acc[j][3] += w * hb3;
        acc[j][4] += w * hb4; acc[j][5] += w * hb5;
        acc[j][6] += w * hb6; acc[j][7] += w * hb7;
      }
    }

    // ---- partials, thread-major: red[tid][b*4 + j] (conflict-free STS.128)
#pragma unroll
    for (int b = 0; b < 8; b++) {
      float4 v;
      v.x = acc[0][b]; v.y = acc[1][b]; v.z = acc[2][b]; v.w = acc[3][b];
      *(float4*)&red[tid * RED_STRIDE + b * 4] = v;
    }
    __syncthreads();

    // ---- reduce 32 K-partials for output (o_h, o_b) ----
    float s0 = 0.f, s1 = 0.f, s2 = 0.f, s3 = 0.f;
    const int rbase = r_th * RED_STRIDE + o_b * 4 + r_j;
#pragma unroll
    for (int q = 0; q < 32; q += 4) {
      s0 += red[(q + 0) * 8 * RED_STRIDE + rbase];
      s1 += red[(q + 1) * 8 * RED_STRIDE + rbase];
      s2 += red[(q + 2) * 8 * RED_STRIDE + rbase];
      s3 += red[(q + 3) * 8 * RED_STRIDE + rbase];
    }
    const float hv = tanhf((s0 + s1) + (s2 + s3) + u);

    // required output (coalesced: warp = 32 consecutive h of one batch)
    out[oidx] = hv;
    // transposed scratch for consumers (scattered scalar, fire-and-forget)
    hT_w_base[(size_t)(t & 1) * 8 * NHID * 8 + (size_t)(hblk + o_h) * 8 + o_b] = hv;

    // ---- per-group barrier: atomic + nanosleep poll, fan-in 16 ----
    __syncthreads();
    __threadfence();
    if (tid == 0) {
      atomicAdd(bar, 1u);
      const unsigned int target = 16u * (unsigned)(t + 1);
      while (*((volatile unsigned int*)bar) < target) {
        __nanosleep(32);
      }
    }
    __syncthreads();
  }
}

// ---------------------------------------------------------------------------
extern "C" void kernel_launch(void* const* d_in, const int* in_sizes, int n_in,
                              void* d_out, int out_size) {
  const float* x     = (const float*)d_in[0];  // (T,B,NIN) f32
  const float* h0    = (const float*)d_in[1];  // (B,NH)    f32
  const float* w_rec = (const float*)d_in[2];  // (NH, NH+NIN+1) f32
  float* out = (float*)d_out;                  // (T,B,NH)  f32

  const int pre_smem = (64 * 132 + 128 * 68 + 64) * (int)sizeof(float);  // 68864 B
  const int rec_smem =
      (NHID * HS_STRIDE + 256 * RED_STRIDE) * (int)sizeof(float);        // 53248 B
  cudaFuncSetAttribute(precompute_kernel,
                       cudaFuncAttributeMaxDynamicSharedMemorySize, pre_smem);
  cudaFuncSetAttribute(rnn_rec_kernel,
                       cudaFuncAttributeMaxDynamicSharedMemorySize, rec_smem);

  dim3 pgrid(TT * BB / 64, NHID / 64);  // 1024 x 8
  precompute_kernel<<<pgrid, 256, pre_smem>>>(x, w_rec);

  rnn_rec_kernel<<<128, 256, rec_smem>>>(h0, w_rec, out);
}